// round 16
// baseline (speedup 1.0000x reference)
#include <cuda_runtime.h>
#include <math.h>

#define NCLS   20
#define NANC   5
#define NB_    64
#define NH_    38
#define NW_    38
#define MAXB_  50
#define SPATIAL 1444
#define CPB    7220            // NANC*SPATIAL
#define NGRP   (CPB / 4)       // 1805 groups of 4 cells
#define NCH    25
#define OBJ_   5.0f
#define K_     0.375f          // THRESH/(1+THRESH)
#define TPB    256
#define GRIDX  8
#define MAXGT  16
#define NBLK   (GRIDX * NB_)   // 512 blocks

// Writeback state (zero-init at load; reset by last block each call)
__device__ float        g_accs[NB_];
__device__ unsigned int g_cnt = 0;

// sigmoid via single-MUFU tanh: sigm(v) = 0.5*tanh(v/2) + 0.5
__device__ __forceinline__ float sigm(float v) {
    float t;
    asm("tanh.approx.f32 %0, %1;" : "=f"(t) : "f"(0.5f * v));
    return fmaf(0.5f, t, 0.5f);
}

__device__ __forceinline__ float ldcg(const float* p) {
    float v;
    asm volatile("ld.global.cg.f32 %0, [%1];" : "=f"(v) : "l"(p));
    return v;
}

__device__ __forceinline__ float iou_full(float x1, float y1, float w1, float h1,
                                          float x2, float y2, float w2, float h2) {
    float cw = fminf(x1 + 0.5f * w1, x2 + 0.5f * w2) - fmaxf(x1 - 0.5f * w1, x2 - 0.5f * w2);
    float ch = fminf(y1 + 0.5f * h1, y2 + 0.5f * h2) - fmaxf(y1 - 0.5f * h1, y2 - 0.5f * h2);
    float inter = (cw <= 0.0f || ch <= 0.0f) ? 0.0f : cw * ch;
    float uni = w1 * h1 + w2 * h2 - inter;
    return inter / uni;
}

// Single launch: grid (8, 64) x 256, reg-capped for 5 blocks/SM.
// Warp 0 self-parses GTs (80 floats, ballot nv, zero extra barriers).
// Hot path: 4 cells/thread. Tail block (x==7, 13/256 hot threads) runs the
// correction on warp 1. Counting last-block writeback with ldcg reads.
__global__ void __launch_bounds__(TPB, 5)
region_single(const float* __restrict__ out,
              const float* __restrict__ tgt,
              const float* __restrict__ anc,
              float* __restrict__ res) {
    const int b = blockIdx.y;
    const int tid = threadIdx.x;
    const bool tailblk = (blockIdx.x == GRIDX - 1);

    __shared__ float  s_t[MAXGT * 5];      // first 16 GT rows only
    __shared__ float4 s_b4[MAXGT];
    __shared__ __align__(16) float s_g2[MAXGT];
    __shared__ int    s_cell[MAXGT];
    __shared__ float4 s_gt4[MAXGT];
    __shared__ float  s_cls[MAXGT];
    __shared__ int    s_nv;
    __shared__ float  wsum[8];

    // ---- hot prefetch first: 5x LDG.128 in flight before anything else ----
    const int group = blockIdx.x * TPB + tid;
    const bool act = (group < NGRP);
    int i0 = 0, j0 = 0;
    float4 v0, v1, v2, v3, v4;
    float aw0 = 0, ah0 = 0;
    if (act) {
        int base = group * 4;
        int a = base / SPATIAL;
        int rem = base - a * SPATIAL;
        j0 = rem / NW_;
        i0 = rem - j0 * NW_;
        const float* op = out + ((size_t)(b * NANC + a)) * NCH * SPATIAL + rem;
        v0 = *(const float4*)(op);
        v1 = *(const float4*)(op + SPATIAL);
        v2 = *(const float4*)(op + 2 * SPATIAL);
        v3 = *(const float4*)(op + 3 * SPATIAL);
        v4 = *(const float4*)(op + 4 * SPATIAL);
        aw0 = __ldg(&anc[2 * a]);
        ah0 = __ldg(&anc[2 * a + 1]);
    }

    // ---- warp-0 minimal parse (overlaps the prefetch's DRAM round trip) ----
    if (tid < 32) {
        const float* trow = tgt + b * MAXB_ * 5;
        float a0 = __ldg(&trow[tid]);
        float a1 = __ldg(&trow[tid + 32]);
        float a2 = (tid < 16) ? __ldg(&trow[tid + 64]) : 0.0f;
        s_t[tid] = a0;
        s_t[tid + 32] = a1;
        if (tid < 16) s_t[tid + 64] = a2;
        __syncwarp();

        const int t = tid;
        float col1 = (t < MAXGT) ? s_t[5 * t + 1] : 1.0f;
        unsigned bal = __ballot_sync(0xFFFFFFFFu, col1 != 0.0f);
        unsigned inv = (~bal) & 0xFFFFu;
        int nv = inv ? (__ffs(inv) - 1) : MAXGT;   // first terminator (k<=15)
        if (t == 0) s_nv = nv;

        if (t < MAXGT) {
            if (t < nv) {
                float cls = s_t[5 * t + 0];
                float gx = s_t[5 * t + 1] * NW_;
                float gy = s_t[5 * t + 2] * NH_;
                float gw = s_t[5 * t + 3] * NW_;
                float gh = s_t[5 * t + 4] * NH_;
                float garea = gw * gh;
                s_b4[t] = make_float4(gx - 0.5f * gw, gx + 0.5f * gw,
                                      gy - 0.5f * gh, gy + 0.5f * gh);
                s_g2[t] = K_ * garea;
                if (tailblk) {
                    // div-free anchor argmax
                    int bn = 0;
                    float aw = __ldg(&anc[0]), ah = __ldg(&anc[1]);
                    float bI = fminf(aw, gw) * fminf(ah, gh);
                    float bU = aw * ah + garea - bI;
                    #pragma unroll
                    for (int q = 1; q < NANC; q++) {
                        float aq = __ldg(&anc[2 * q]), hq = __ldg(&anc[2 * q + 1]);
                        float I = fminf(aq, gw) * fminf(hq, gh);
                        float U = aq * hq + garea - I;
                        if (I * bU > bI * U) { bI = I; bU = U; bn = q; }
                    }
                    int gi = min(max((int)gx, 0), NW_ - 1);
                    int gj = min(max((int)gy, 0), NH_ - 1);
                    s_cell[t] = (bn * NH_ + gj) * NW_ + gi;
                    s_gt4[t] = make_float4(gx, gy, gw, gh);
                    s_cls[t] = cls;
                }
            } else {
                s_b4[t] = make_float4(1e30f, -1e30f, 1e30f, -1e30f);
                s_g2[t] = 1e30f;
                if (tailblk) s_cell[t] = -1;
            }
        }
    }
    __syncthreads();
    const int nv = s_nv;
    const int nvp = (nv + 3) & ~3;

    float contrib = 0.0f;

    if (act) {
        // ---------------- hot path: 4 cells per thread ----------
        float o0[4] = {v0.x, v0.y, v0.z, v0.w};
        float o1[4] = {v1.x, v1.y, v1.z, v1.w};
        float o2[4] = {v2.x, v2.y, v2.z, v2.w};
        float o3[4] = {v3.x, v3.y, v3.z, v3.w};
        float o4[4] = {v4.x, v4.y, v4.z, v4.w};

        float pxl[4], pxr[4], pyl[4], pyr[4], c0[4], cf2[4], m[4];
        #pragma unroll
        for (int c = 0; c < 4; c++) {
            float x = sigm(o0[c]), y = sigm(o1[c]), conf = sigm(o4[c]);
            int ii = i0 + c, jj = j0;
            if (ii >= NW_) { ii -= NW_; jj++; }
            float px = x + (float)ii, py = y + (float)jj;
            float pw = __expf(o2[c]) * aw0, ph = __expf(o3[c]) * ah0;
            pxl[c] = px - 0.5f * pw; pxr[c] = px + 0.5f * pw;
            pyl[c] = py - 0.5f * ph; pyr[c] = py + 0.5f * ph;
            c0[c] = K_ * pw * ph;
            float dx = x - 0.5f, dy = y - 0.5f;
            contrib += 0.5f * (dx * dx + dy * dy + o2[c] * o2[c] + o3[c] * o3[c]);
            cf2[c] = 0.5f * conf * conf;
            m[c] = -1e30f;
        }

        for (int t = 0; t < nvp; t += 4) {
            float4 gg = *(const float4*)&s_g2[t];
            float gA[4] = {gg.x, gg.y, gg.z, gg.w};
            #pragma unroll
            for (int u = 0; u < 4; u++) {
                float4 g = s_b4[t + u];
                float g2 = gA[u];
                #pragma unroll
                for (int c = 0; c < 4; c++) {
                    float cw = fmaxf(fminf(pxr[c], g.y) - fmaxf(pxl[c], g.x), 0.0f);
                    float ch = fminf(pyr[c], g.w) - fmaxf(pyl[c], g.z);
                    m[c] = fmaxf(m[c], fmaf(cw, ch, -g2));
                }
            }
        }
        #pragma unroll
        for (int c = 0; c < 4; c++)
            if (m[c] <= c0[c]) contrib += cf2[c];
    } else if (tailblk && tid >= 32 && tid < 64) {
        // -------- correction: warp 1 of the (mostly idle) tail block --------
        const int c = tid - 32;
        if (c < nv) {
            int mycell = s_cell[c];
            bool winner = true;                    // last-writer-wins scatter
            for (int u = c + 1; u < nv; u++)
                if (s_cell[u] == mycell) winner = false;
            if (winner) {
                float4 gt = s_gt4[c];
                float gx = gt.x, gy = gt.y, gw = gt.z, gh = gt.w;
                float cls = s_cls[c];
                int bn = mycell / SPATIAL;
                int rem = mycell - bn * SPATIAL;
                int gj = rem / NW_;
                int gi = rem - gj * NW_;

                const float* op = out + ((size_t)(b * NANC + bn)) * NCH * SPATIAL
                                  + gj * NW_ + gi;
                float o0 = __ldg(&op[0]), o1 = __ldg(&op[SPATIAL]),
                      o2 = __ldg(&op[2 * SPATIAL]), o3 = __ldg(&op[3 * SPATIAL]),
                      o4 = __ldg(&op[4 * SPATIAL]);
                float aw = __ldg(&anc[2 * bn]), ah = __ldg(&anc[2 * bn + 1]);

                float x = sigm(o0), y = sigm(o1), conf = sigm(o4);
                float px = x + (float)gi, py = y + (float)gj;
                float pw = __expf(o2) * aw, ph = __expf(o3) * ah;
                float pxl = px - 0.5f * pw, pxr = px + 0.5f * pw;
                float pyl = py - 0.5f * ph, pyr = py + 0.5f * ph;
                float c0 = K_ * pw * ph;
                int over = 0;
                for (int u = 0; u < nv; u++) {
                    float4 g = s_b4[u];
                    float cw = fminf(pxr, g.y) - fmaxf(pxl, g.x);
                    float ch = fminf(pyr, g.w) - fmaxf(pyl, g.z);
                    if (cw > 0.0f && ch > 0.0f && cw * ch > c0 + s_g2[u]) over = 1;
                }
                float dxn = x - 0.5f, dyn = y - 0.5f;
                float noobj = 0.5f * (dxn * dxn + dyn * dyn + o2 * o2 + o3 * o3)
                            + (over ? 0.0f : 0.5f * conf * conf);

                float tx = gx - (float)gi, ty = gy - (float)gj;
                float tw = logf(gw / aw), th = logf(gh / ah);
                float tconf = iou_full(gx, gy, gw, gh, px, py, pw, ph);
                float dx = x - tx, dy = y - ty, dw = o2 - tw, dh = o3 - th,
                      dc = conf - tconf;
                float obj = 0.5f * (dx * dx + dy * dy + dw * dw + dh * dh
                                    + OBJ_ * dc * dc);
                const float* cp = op + 5 * SPATIAL;
                float mm = -1e30f;
                #pragma unroll
                for (int q = 0; q < NCLS; q++) mm = fmaxf(mm, __ldg(&cp[q * SPATIAL]));
                float s = 0.0f;
                #pragma unroll
                for (int q = 0; q < NCLS; q++) s += expf(__ldg(&cp[q * SPATIAL]) - mm);
                obj += (mm + logf(s)) - __ldg(&cp[(int)cls * SPATIAL]);

                contrib = obj - noobj;
            }
        }
    }

    // ---- block reduce + counting last-block writeback ----
    #pragma unroll
    for (int o = 16; o > 0; o >>= 1)
        contrib += __shfl_down_sync(0xFFFFFFFFu, contrib, o);
    if ((tid & 31) == 0) wsum[tid >> 5] = contrib;
    __syncthreads();
    if (tid == 0) {
        float v = 0.0f;
        #pragma unroll
        for (int q = 0; q < 8; q++) v += wsum[q];
        atomicAdd(&g_accs[b], v);              // 8 blocks per address
        __threadfence();
        unsigned prev = atomicAdd(&g_cnt, 1u);
        if (prev == NBLK - 1) {
            __threadfence();                   // acquire: all g_accs visible in L2
            float total = 0.0f;
            #pragma unroll 16
            for (int q = 0; q < NB_; q++)
                total += ldcg(&g_accs[q]);     // pipelined L2 loads, no atomics
            res[0] = total;
            // reset for next graph replay
            for (int q = 0; q < NB_; q++) g_accs[q] = 0.0f;
            __threadfence();
            g_cnt = 0u;
        }
    }
}

extern "C" void kernel_launch(void* const* d_in, const int* in_sizes, int n_in,
                              void* d_out, int out_size) {
    const float* out = (const float*)d_in[0];
    const float* tgt = (const float*)d_in[1];
    const float* anc = (const float*)d_in[2];
    float* res = (float*)d_out;

    dim3 grid(GRIDX, NB_);
    region_single<<<grid, TPB>>>(out, tgt, anc, res);
}

// round 17
// speedup vs baseline: 1.0638x; 1.0638x over previous
#include <cuda_runtime.h>
#include <math.h>

#define NCLS   20
#define NANC   5
#define NB_    64
#define NH_    38
#define NW_    38
#define MAXB_  50
#define SPATIAL 1444
#define CPB    7220            // NANC*SPATIAL
#define NGRP2  (CPB / 2)       // 3610 groups of 2 cells
#define NCH    25
#define OBJ_   5.0f
#define K_     0.375f          // THRESH/(1+THRESH)
#define TPB    256
#define GRIDX  15              // hot slices; x==GRIDX = correction slice
#define MAXGT  16

// Scratch written by prep each call
__device__ int    g_nv[NB_];
__device__ float4 g_b4[NB_ * MAXGT];   // xl, xr, yl, yr
__device__ float  g_g2[NB_ * MAXGT];   // K * gw * gh
__device__ int    g_cell[NB_ * MAXGT];
__device__ float4 g_gt4[NB_ * MAXGT];  // gx, gy, gw, gh
__device__ float  g_cls[NB_ * MAXGT];

// sigmoid via single-MUFU tanh: sigm(v) = 0.5*tanh(v/2) + 0.5
__device__ __forceinline__ float sigm(float v) {
    float t;
    asm("tanh.approx.f32 %0, %1;" : "=f"(t) : "f"(0.5f * v));
    return fmaf(0.5f, t, 0.5f);
}

__device__ __forceinline__ float iou_full(float x1, float y1, float w1, float h1,
                                          float x2, float y2, float w2, float h2) {
    float cw = fminf(x1 + 0.5f * w1, x2 + 0.5f * w2) - fmaxf(x1 - 0.5f * w1, x2 - 0.5f * w2);
    float ch = fminf(y1 + 0.5f * h1, y2 + 0.5f * h2) - fmaxf(y1 - 0.5f * h1, y2 - 0.5f * h2);
    float inter = (cw <= 0.0f || ch <= 0.0f) ? 0.0f : cw * ch;
    float uni = w1 * h1 + w2 * h2 - inter;
    return inter / uni;
}

// ---------------------------------------------------------------------------
// Prep (lean): 64 blocks x 64 threads, coalesced parse only.
// Signals PDL completion as soon as its outputs are globally visible.
// ---------------------------------------------------------------------------
__global__ void __launch_bounds__(64)
region_prep(const float* __restrict__ tgt,
            const float* __restrict__ anc,
            float* __restrict__ res) {
    const int b = blockIdx.x;
    const int t = threadIdx.x;

    __shared__ float s_t[MAXB_ * 5];
    __shared__ int   s_nv;

    if (t == 0) {
        s_nv = MAXB_;
        if (b == 0) res[0] = 0.0f;
    }
    const float* trow = tgt + b * MAXB_ * 5;
    #pragma unroll
    for (int k = 0; k < 4; k++) {
        int idx = t + 64 * k;
        if (idx < MAXB_ * 5) s_t[idx] = trow[idx];
    }
    __syncthreads();

    if (t < MAXB_ && s_t[t * 5 + 1] == 0.0f) atomicMin(&s_nv, t);
    __syncthreads();
    const int nv = s_nv;
    if (t == 0) g_nv[b] = nv;

    if (t < MAXGT) {
        if (t < nv) {
            float cls = s_t[t * 5 + 0];
            float gx = s_t[t * 5 + 1] * NW_;
            float gy = s_t[t * 5 + 2] * NH_;
            float gw = s_t[t * 5 + 3] * NW_;
            float gh = s_t[t * 5 + 4] * NH_;
            float garea = gw * gh;
            // div-free anchor argmax: I1/U1 > I2/U2 <=> I1*U2 > I2*U1
            int bn = 0;
            float aw = __ldg(&anc[0]), ah = __ldg(&anc[1]);
            float bI = fminf(aw, gw) * fminf(ah, gh);
            float bU = aw * ah + garea - bI;
            #pragma unroll
            for (int q = 1; q < NANC; q++) {
                float aq = __ldg(&anc[2 * q]), hq = __ldg(&anc[2 * q + 1]);
                float I = fminf(aq, gw) * fminf(hq, gh);
                float U = aq * hq + garea - I;
                if (I * bU > bI * U) { bI = I; bU = U; bn = q; }
            }
            int gi = min(max((int)gx, 0), NW_ - 1);
            int gj = min(max((int)gy, 0), NH_ - 1);
            g_cell[b * MAXGT + t] = (bn * NH_ + gj) * NW_ + gi;
            g_b4[b * MAXGT + t] = make_float4(gx - 0.5f * gw, gx + 0.5f * gw,
                                              gy - 0.5f * gh, gy + 0.5f * gh);
            g_g2[b * MAXGT + t] = K_ * garea;
            g_gt4[b * MAXGT + t] = make_float4(gx, gy, gw, gh);
            g_cls[b * MAXGT + t] = cls;
        } else {
            g_b4[b * MAXGT + t] = make_float4(1e30f, -1e30f, 1e30f, -1e30f);
            g_g2[b * MAXGT + t] = 1e30f;
            g_cell[b * MAXGT + t] = -1;
        }
    }
    // make outputs visible, then allow the dependent grid to launch
    __threadfence();
    cudaTriggerProgrammaticLaunchCompletion();
}

// ---------------------------------------------------------------------------
// Main: grid (GRIDX+1, 64) x 256, launched with PDL. Prefetch first (overlaps
// the prep kernel), then grid-dependency sync, then consume g_*.
// ---------------------------------------------------------------------------
__global__ void __launch_bounds__(TPB, 6)
region_main(const float* __restrict__ out,
            const float* __restrict__ anc,
            float* __restrict__ res) {
    const int b = blockIdx.y;
    const int tid = threadIdx.x;

    __shared__ float4 s_b4[MAXGT];
    __shared__ __align__(16) float s_g2[MAXGT];

    if (blockIdx.x < GRIDX) {
        // ---------------- hot path: 2 cells per thread ----------------
        const int group = blockIdx.x * TPB + tid;
        const bool act = (group < NGRP2);
        int i0 = 0, j0 = 0;
        float2 v0, v1, v2, v3, v4;
        float aw0 = 0, ah0 = 0;
        if (act) {
            int base = group * 2;
            int a = base / SPATIAL;
            int rem = base - a * SPATIAL;
            j0 = rem / NW_;
            i0 = rem - j0 * NW_;
            const float* op = out + ((size_t)(b * NANC + a)) * NCH * SPATIAL + rem;
            v0 = *(const float2*)(op);
            v1 = *(const float2*)(op + SPATIAL);
            v2 = *(const float2*)(op + 2 * SPATIAL);
            v3 = *(const float2*)(op + 3 * SPATIAL);
            v4 = *(const float2*)(op + 4 * SPATIAL);
            aw0 = __ldg(&anc[2 * a]);
            ah0 = __ldg(&anc[2 * a + 1]);
        }
        // wait for prep's outputs (prefetch above already in flight)
        cudaGridDependencySynchronize();
        if (tid < MAXGT) {
            s_b4[tid] = g_b4[b * MAXGT + tid];
            s_g2[tid] = g_g2[b * MAXGT + tid];
        }
        const int nv = __ldg(&g_nv[b]);
        const int nvp = (nv + 3) & ~3;
        __syncthreads();

        float contrib = 0.0f;
        if (act) {
            float o0[2] = {v0.x, v0.y};
            float o1[2] = {v1.x, v1.y};
            float o2[2] = {v2.x, v2.y};
            float o3[2] = {v3.x, v3.y};
            float o4[2] = {v4.x, v4.y};

            float pxl[2], pxr[2], pyl[2], pyr[2], c0[2], cf2[2], m[2];
            #pragma unroll
            for (int c = 0; c < 2; c++) {
                float x = sigm(o0[c]), y = sigm(o1[c]), conf = sigm(o4[c]);
                int ii = i0 + c, jj = j0;
                if (ii >= NW_) { ii -= NW_; jj++; }
                float px = x + (float)ii, py = y + (float)jj;
                float pw = __expf(o2[c]) * aw0, ph = __expf(o3[c]) * ah0;
                pxl[c] = px - 0.5f * pw; pxr[c] = px + 0.5f * pw;
                pyl[c] = py - 0.5f * ph; pyr[c] = py + 0.5f * ph;
                c0[c] = K_ * pw * ph;
                float dx = x - 0.5f, dy = y - 0.5f;
                contrib += 0.5f * (dx * dx + dy * dy + o2[c] * o2[c] + o3[c] * o3[c]);
                cf2[c] = 0.5f * conf * conf;
                m[c] = -1e30f;
            }
            for (int t = 0; t < nvp; t += 4) {
                float4 gg = *(const float4*)&s_g2[t];
                float gA[4] = {gg.x, gg.y, gg.z, gg.w};
                #pragma unroll
                for (int u = 0; u < 4; u++) {
                    float4 g = s_b4[t + u];
                    float g2 = gA[u];
                    #pragma unroll
                    for (int c = 0; c < 2; c++) {
                        float cw = fmaxf(fminf(pxr[c], g.y) - fmaxf(pxl[c], g.x), 0.0f);
                        float ch = fminf(pyr[c], g.w) - fmaxf(pyl[c], g.z);
                        m[c] = fmaxf(m[c], fmaf(cw, ch, -g2));
                    }
                }
            }
            #pragma unroll
            for (int c = 0; c < 2; c++)
                if (m[c] <= c0[c]) contrib += cf2[c];
        }

        #pragma unroll
        for (int o = 16; o > 0; o >>= 1)
            contrib += __shfl_down_sync(0xFFFFFFFFu, contrib, o);
        __shared__ float wsum[8];
        if ((tid & 31) == 0) wsum[tid >> 5] = contrib;
        __syncthreads();
        if (tid == 0) {
            float v = 0.0f;
            #pragma unroll
            for (int q = 0; q < 8; q++) v += wsum[q];
            atomicAdd(res, v);
        }
    } else {
        // ---------------- correction block (one per batch) ----------------
        cudaGridDependencySynchronize();
        if (tid < MAXGT) {
            s_b4[tid] = g_b4[b * MAXGT + tid];
            s_g2[tid] = g_g2[b * MAXGT + tid];
        }
        const int nv = __ldg(&g_nv[b]);
        __syncthreads();

        float corr = 0.0f;
        if (tid < nv) {
            int mycell = g_cell[b * MAXGT + tid];
            bool winner = true;                    // last-writer-wins
            for (int u = tid + 1; u < nv; u++)
                if (g_cell[b * MAXGT + u] == mycell) winner = false;
            if (winner) {
                float4 gt = g_gt4[b * MAXGT + tid];
                float gx = gt.x, gy = gt.y, gw = gt.z, gh = gt.w;
                float cls = g_cls[b * MAXGT + tid];
                int bn = mycell / SPATIAL;
                int rem = mycell - bn * SPATIAL;
                int gj = rem / NW_;
                int gi = rem - gj * NW_;

                const float* op = out + ((size_t)(b * NANC + bn)) * NCH * SPATIAL
                                  + gj * NW_ + gi;
                float o0 = op[0], o1 = op[SPATIAL], o2 = op[2 * SPATIAL],
                      o3 = op[3 * SPATIAL], o4 = op[4 * SPATIAL];
                float aw = __ldg(&anc[2 * bn]), ah = __ldg(&anc[2 * bn + 1]);

                // SAME sigm as hot path so the noobj subtraction cancels exactly
                float x = sigm(o0), y = sigm(o1), conf = sigm(o4);
                float px = x + (float)gi, py = y + (float)gj;
                float pw = __expf(o2) * aw, ph = __expf(o3) * ah;
                float pxl = px - 0.5f * pw, pxr = px + 0.5f * pw;
                float pyl = py - 0.5f * ph, pyr = py + 0.5f * ph;
                float c0 = K_ * pw * ph;
                int over = 0;
                for (int u = 0; u < nv; u++) {
                    float4 g = s_b4[u];
                    float cw = fminf(pxr, g.y) - fmaxf(pxl, g.x);
                    float ch = fminf(pyr, g.w) - fmaxf(pyl, g.z);
                    if (cw > 0.0f && ch > 0.0f && cw * ch > c0 + s_g2[u]) over = 1;
                }
                float dxn = x - 0.5f, dyn = y - 0.5f;
                float noobj = 0.5f * (dxn * dxn + dyn * dyn + o2 * o2 + o3 * o3)
                            + (over ? 0.0f : 0.5f * conf * conf);

                float tx = gx - (float)gi, ty = gy - (float)gj;
                float tw = logf(gw / aw), th = logf(gh / ah);
                float tconf = iou_full(gx, gy, gw, gh, px, py, pw, ph);
                float dx = x - tx, dy = y - ty, dw = o2 - tw, dh = o3 - th,
                      dc = conf - tconf;
                float obj = 0.5f * (dx * dx + dy * dy + dw * dw + dh * dh
                                    + OBJ_ * dc * dc);
                const float* cp = op + 5 * SPATIAL;
                float mm = -1e30f;
                #pragma unroll
                for (int c = 0; c < NCLS; c++) mm = fmaxf(mm, cp[c * SPATIAL]);
                float s = 0.0f;
                #pragma unroll
                for (int c = 0; c < NCLS; c++) s += expf(cp[c * SPATIAL] - mm);
                obj += (mm + logf(s)) - cp[(int)cls * SPATIAL];

                corr = obj - noobj;
            }
        }
        if (tid < 32) {
            #pragma unroll
            for (int o = 16; o > 0; o >>= 1)
                corr += __shfl_down_sync(0xFFFFFFFFu, corr, o);
            if (tid == 0) atomicAdd(res, corr);
        }
    }
}

extern "C" void kernel_launch(void* const* d_in, const int* in_sizes, int n_in,
                              void* d_out, int out_size) {
    const float* out = (const float*)d_in[0];
    const float* tgt = (const float*)d_in[1];
    const float* anc = (const float*)d_in[2];
    float* res = (float*)d_out;

    region_prep<<<NB_, 64>>>(tgt, anc, res);

    // Main launched with Programmatic Dependent Launch: its blocks may start
    // while prep runs; they prefetch independent data, then grid-sync.
    cudaLaunchConfig_t cfg = {};
    cfg.gridDim = dim3(GRIDX + 1, NB_);
    cfg.blockDim = dim3(TPB);
    cfg.dynamicSmemBytes = 0;
    cudaLaunchAttribute attrs[1];
    attrs[0].id = cudaLaunchAttributeProgrammaticStreamSerialization;
    attrs[0].val.programmaticStreamSerializationAllowed = 1;
    cfg.attrs = attrs;
    cfg.numAttrs = 1;
    cudaLaunchKernelEx(&cfg, region_main, out, anc, res);
}